// round 1
// baseline (speedup 1.0000x reference)
#include <cuda_runtime.h>
#include <cstdint>

// AxialAttention: 512 independent attention problems of [S=512, c=64].
// Batch B' = outer*8 + W, outer=(b*8+h)*4+t in [0,64), W in [0,8).
// q/k/v/out element (B', s, c) lives at outer*262144 + s*512 + W*64 + c.
// attn output: [B',512,512] contiguous, placed after `out` in d_out.

#define QSTR 68          // Q smem row stride (floats)
#define KSTR 68          // K smem row stride
#define VSTR 72          // V smem row stride
#define SSTR 516         // scores smem row stride
#define SMEM_FLOATS (64*QSTR + 128*VSTR + 64*SSTR)

__device__ __forceinline__ uint32_t f2tf32(float x) {
    uint32_t r; asm("cvt.rna.tf32.f32 %0, %1;" : "=r"(r) : "f"(x)); return r;
}

__device__ __forceinline__ void mma8(float* c,
        uint32_t a0, uint32_t a1, uint32_t a2, uint32_t a3,
        uint32_t b0, uint32_t b1) {
    asm volatile(
        "mma.sync.aligned.m16n8k8.row.col.f32.tf32.tf32.f32 "
        "{%0,%1,%2,%3},{%4,%5,%6,%7},{%8,%9},{%0,%1,%2,%3};\n"
        : "+f"(c[0]), "+f"(c[1]), "+f"(c[2]), "+f"(c[3])
        : "r"(a0), "r"(a1), "r"(a2), "r"(a3), "r"(b0), "r"(b1));
}

__global__ __launch_bounds__(256, 1)
void axial_attn_kernel(const float* __restrict__ q,
                       const float* __restrict__ k,
                       const float* __restrict__ v,
                       const int*   __restrict__ amask,
                       const float* __restrict__ hmask,
                       float* __restrict__ outp,
                       float* __restrict__ attnp)
{
    extern __shared__ float sm[];
    float* Qs  = sm;                  // 64 x QSTR
    float* KVs = Qs + 64 * QSTR;      // 128 x VSTR (K phase uses stride KSTR)
    float* Sc  = KVs + 128 * VSTR;    // 64 x SSTR

    const int tid  = threadIdx.x;
    const int w    = tid >> 5;
    const int lane = tid & 31;
    const int gid  = lane >> 2;   // groupID (row within fragment)
    const int tig  = lane & 3;    // thread-in-group

    const int Bp    = blockIdx.y;           // 0..511
    const int q0    = blockIdx.x * 64;      // query tile base row
    const int outer = Bp >> 3;
    const int Wd    = Bp & 7;
    const long base = (long)outer * 262144 + (long)Wd * 64;

    const float* qb = q + base;
    const float* kb = k + base;
    const float* vb = v + base;
    float* ob = outp + base;
    float* ab = attnp + (long)Bp * 262144;

    // ---- load Q tile (scale by 1/sqrt(64)=0.125, convert tf32) ----
    #pragma unroll
    for (int p = 0; p < 4; p++) {
        int r  = p * 16 + (tid >> 4);
        int c4 = (tid & 15) * 4;
        float4 t = *(const float4*)(qb + (long)(q0 + r) * 512 + c4);
        float4 s;
        s.x = __uint_as_float(f2tf32(t.x * 0.125f));
        s.y = __uint_as_float(f2tf32(t.y * 0.125f));
        s.z = __uint_as_float(f2tf32(t.z * 0.125f));
        s.w = __uint_as_float(f2tf32(t.w * 0.125f));
        *(float4*)(Qs + r * QSTR + c4) = s;
    }
    __syncthreads();

    // ---- preload A fragments (Q rows m0..m0+15, full k=64) ----
    const int m0 = (w >> 1) * 16;
    const int cb = (w & 1) * 64;   // column sub-block within a 128-col K chunk
    uint32_t A[8][4];
    #pragma unroll
    for (int ks = 0; ks < 8; ks++) {
        const float* qr = Qs + (m0 + gid) * QSTR + ks * 8 + tig;
        A[ks][0] = __float_as_uint(qr[0]);
        A[ks][1] = __float_as_uint(qr[8 * QSTR]);
        A[ks][2] = __float_as_uint(qr[4]);
        A[ks][3] = __float_as_uint(qr[8 * QSTR + 4]);
    }

    // ---- QK^T: 4 chunks of 128 key rows ----
    for (int kc = 0; kc < 4; kc++) {
        __syncthreads();
        #pragma unroll
        for (int p = 0; p < 8; p++) {
            int r  = p * 16 + (tid >> 4);
            int c4 = (tid & 15) * 4;
            float4 t = *(const float4*)(kb + (long)(kc * 128 + r) * 512 + c4);
            float4 s;
            s.x = __uint_as_float(f2tf32(t.x));
            s.y = __uint_as_float(f2tf32(t.y));
            s.z = __uint_as_float(f2tf32(t.z));
            s.w = __uint_as_float(f2tf32(t.w));
            *(float4*)(KVs + r * KSTR + c4) = s;
        }
        __syncthreads();

        float C[8][4];
        #pragma unroll
        for (int nt = 0; nt < 8; nt++)
            #pragma unroll
            for (int i = 0; i < 4; i++) C[nt][i] = 0.f;

        #pragma unroll
        for (int nt = 0; nt < 8; nt++) {
            const float* kr = KVs + (cb + nt * 8 + gid) * KSTR + tig;
            #pragma unroll
            for (int ks = 0; ks < 8; ks++) {
                uint32_t b0 = __float_as_uint(kr[ks * 8]);
                uint32_t b1 = __float_as_uint(kr[ks * 8 + 4]);
                mma8(C[nt], A[ks][0], A[ks][1], A[ks][2], A[ks][3], b0, b1);
            }
        }
        // store raw scores to smem
        #pragma unroll
        for (int nt = 0; nt < 8; nt++) {
            int col = kc * 128 + cb + nt * 8 + tig * 2;
            float* s0 = Sc + (m0 + gid) * SSTR + col;
            s0[0] = C[nt][0];
            s0[1] = C[nt][1];
            s0[8 * SSTR]     = C[nt][2];
            s0[8 * SSTR + 1] = C[nt][3];
        }
    }
    __syncthreads();

    // ---- masked softmax + head_mask, write attn, store P (tf32) to smem ----
    for (int rr = 0; rr < 8; rr++) {
        int r    = w * 8 + rr;
        int qrow = q0 + r;
        float*       srow = Sc + r * SSTR;
        const int*   mrow = amask + (long)qrow * 512;

        float sv[16];
        float mx = -INFINITY;
        #pragma unroll
        for (int j = 0; j < 16; j++) {
            int col = lane + j * 32;
            float s = srow[col];
            s = (mrow[col] != 0) ? s : -INFINITY;
            sv[j] = s;
            mx = fmaxf(mx, s);
        }
        #pragma unroll
        for (int o = 16; o; o >>= 1) mx = fmaxf(mx, __shfl_xor_sync(0xFFFFFFFFu, mx, o));

        float sum = 0.f;
        #pragma unroll
        for (int j = 0; j < 16; j++) {
            float e = __expf(sv[j] - mx);
            sv[j] = e;
            sum += e;
        }
        #pragma unroll
        for (int o = 16; o; o >>= 1) sum += __shfl_xor_sync(0xFFFFFFFFu, sum, o);
        float inv = 1.0f / sum;

        const float* hrow = hmask + (long)qrow * 512;
        float*       arow = ab + (long)qrow * 512;
        #pragma unroll
        for (int j = 0; j < 16; j++) {
            int col = lane + j * 32;
            float a = sv[j] * inv * hrow[col];
            arow[col] = a;
            srow[col] = __uint_as_float(f2tf32(a));
        }
    }
    __syncthreads();

    // ---- O = P @ V ----
    const int obf = (w & 1) * 32;
    float O[4][4];
    #pragma unroll
    for (int nt = 0; nt < 4; nt++)
        #pragma unroll
        for (int i = 0; i < 4; i++) O[nt][i] = 0.f;

    for (int kc = 0; kc < 4; kc++) {
        __syncthreads();
        #pragma unroll
        for (int p = 0; p < 8; p++) {
            int r  = p * 16 + (tid >> 4);
            int c4 = (tid & 15) * 4;
            float4 t = *(const float4*)(vb + (long)(kc * 128 + r) * 512 + c4);
            float4 s;
            s.x = __uint_as_float(f2tf32(t.x));
            s.y = __uint_as_float(f2tf32(t.y));
            s.z = __uint_as_float(f2tf32(t.z));
            s.w = __uint_as_float(f2tf32(t.w));
            *(float4*)(KVs + r * VSTR + c4) = s;
        }
        __syncthreads();

        #pragma unroll
        for (int ks = 0; ks < 16; ks++) {
            const float* pr = Sc + (m0 + gid) * SSTR + kc * 128 + ks * 8 + tig;
            uint32_t a0 = __float_as_uint(pr[0]);
            uint32_t a1 = __float_as_uint(pr[8 * SSTR]);
            uint32_t a2 = __float_as_uint(pr[4]);
            uint32_t a3 = __float_as_uint(pr[8 * SSTR + 4]);
            const float* vr = KVs + (ks * 8 + tig) * VSTR + obf + gid;
            #pragma unroll
            for (int nt = 0; nt < 4; nt++) {
                uint32_t b0 = __float_as_uint(vr[nt * 8]);
                uint32_t b1 = __float_as_uint(vr[4 * VSTR + nt * 8]);
                mma8(O[nt], a0, a1, a2, a3, b0, b1);
            }
        }
    }

    // ---- write out tile ----
    #pragma unroll
    for (int nt = 0; nt < 4; nt++) {
        int col = obf + nt * 8 + tig * 2;
        float* o0 = ob + (long)(q0 + m0 + gid) * 512 + col;
        o0[0] = O[nt][0];
        o0[1] = O[nt][1];
        float* o1 = ob + (long)(q0 + m0 + gid + 8) * 512 + col;
        o1[0] = O[nt][2];
        o1[1] = O[nt][3];
    }
}

extern "C" void kernel_launch(void* const* d_in, const int* in_sizes, int n_in,
                              void* d_out, int out_size) {
    const float* q  = (const float*)d_in[0];
    const float* k  = (const float*)d_in[1];
    const float* v  = (const float*)d_in[2];
    const int*   am = (const int*)d_in[3];
    const float* hm = (const float*)d_in[4];

    float* out  = (float*)d_out;
    float* attn = out + (long)in_sizes[0];   // attn follows `out` (16,777,216 floats)

    size_t smem = (size_t)SMEM_FLOATS * sizeof(float);
    cudaFuncSetAttribute(axial_attn_kernel,
                         cudaFuncAttributeMaxDynamicSharedMemorySize, (int)smem);

    dim3 grid(8, 512);   // x: query tile (64 rows each), y: flattened batch B'
    axial_attn_kernel<<<grid, 256, smem>>>(q, k, v, am, hm, out, attn);
}

// round 2
// speedup vs baseline: 1.2200x; 1.2200x over previous
#include <cuda_runtime.h>
#include <cstdint>

// AxialAttention: 512 independent attention problems of [S=512, c=64].
// B' = outer*8 + W; q/k/v/out element (B', s, c) at outer*262144 + s*512 + W*64 + c.
// attn output [B',512,512] contiguous, placed after `out` in d_out.
// 32 query rows per CTA, 256 threads, double-buffered cp.async K/V chunks (64 rows).

#define QSTR 68
#define KSTR 68
#define VSTR 72
#define SSTR 516
#define QROWS 32
#define KVBUF (64*VSTR)
#define SMEM_FLOATS (QROWS*QSTR + 2*KVBUF + QROWS*SSTR)

__device__ __forceinline__ uint32_t f2tf32(float x) {
    uint32_t r; asm("cvt.rna.tf32.f32 %0, %1;" : "=r"(r) : "f"(x)); return r;
}

__device__ __forceinline__ void mma8(float* c,
        uint32_t a0, uint32_t a1, uint32_t a2, uint32_t a3,
        uint32_t b0, uint32_t b1) {
    asm volatile(
        "mma.sync.aligned.m16n8k8.row.col.f32.tf32.tf32.f32 "
        "{%0,%1,%2,%3},{%4,%5,%6,%7},{%8,%9},{%0,%1,%2,%3};\n"
        : "+f"(c[0]), "+f"(c[1]), "+f"(c[2]), "+f"(c[3])
        : "r"(a0), "r"(a1), "r"(a2), "r"(a3), "r"(b0), "r"(b1));
}

__device__ __forceinline__ void cp16(float* s, const float* g) {
    uint32_t sa = (uint32_t)__cvta_generic_to_shared(s);
    asm volatile("cp.async.cg.shared.global [%0], [%1], 16;\n" :: "r"(sa), "l"(g));
}
#define CP_COMMIT asm volatile("cp.async.commit_group;\n" ::: "memory")
#define CP_WAIT1  asm volatile("cp.async.wait_group 1;\n" ::: "memory")
#define CP_WAIT0  asm volatile("cp.async.wait_group 0;\n" ::: "memory")

// load a 64-row x 64-col fp32 chunk into smem (raw bits, converted at use)
__device__ __forceinline__ void load_chunk(float* dst, const float* gb,
                                           int row0, int str, int tid) {
    #pragma unroll
    for (int i = 0; i < 4; i++) {
        int idx = tid + 256 * i;        // 1024 float4 total
        int r   = idx >> 4;
        int c4  = (idx & 15) << 2;
        cp16(dst + r * str + c4, gb + (long)(row0 + r) * 512 + c4);
    }
}

__global__ __launch_bounds__(256, 2)
void axial_attn_kernel(const float* __restrict__ q,
                       const float* __restrict__ k,
                       const float* __restrict__ v,
                       const int*   __restrict__ amask,
                       const float* __restrict__ hmask,
                       float* __restrict__ outp,
                       float* __restrict__ attnp)
{
    extern __shared__ float sm[];
    float* Qs = sm;                         // QROWS x QSTR (tf32, pre-scaled)
    float* KV = Qs + QROWS * QSTR;          // 2 x KVBUF (raw fp32 via cp.async)
    float* Sc = KV + 2 * KVBUF;             // QROWS x SSTR

    const int tid  = threadIdx.x;
    const int w    = tid >> 5;
    const int lane = tid & 31;
    const int gid  = lane >> 2;
    const int tig  = lane & 3;
    const int rg   = w >> 2;       // row group (0/1) -> 16 rows
    const int cg   = w & 3;        // col group (0..3) -> 16 cols within chunk
    const int m0   = rg * 16;

    const int Bp    = blockIdx.y;
    const int q0    = blockIdx.x * QROWS;
    const int outer = Bp >> 3;
    const int Wd    = Bp & 7;
    const long base = (long)outer * 262144 + (long)Wd * 64;

    const float* qb = q + base;
    const float* kb = k + base;
    const float* vb = v + base;
    float* ob = outp + base;
    float* ab = attnp + (long)Bp * 262144;

    // kick off K chunk 0 fetch immediately
    load_chunk(KV, kb, 0, KSTR, tid);
    CP_COMMIT;

    // ---- load Q tile (scale by 0.125, convert tf32) ----
    #pragma unroll
    for (int i = 0; i < 2; i++) {
        int idx = tid + 256 * i;            // 512 float4
        int r   = idx >> 4;
        int c4  = (idx & 15) << 2;
        float4 t = *(const float4*)(qb + (long)(q0 + r) * 512 + c4);
        float4 s;
        s.x = __uint_as_float(f2tf32(t.x * 0.125f));
        s.y = __uint_as_float(f2tf32(t.y * 0.125f));
        s.z = __uint_as_float(f2tf32(t.z * 0.125f));
        s.w = __uint_as_float(f2tf32(t.w * 0.125f));
        *(float4*)(Qs + r * QSTR + c4) = s;
    }
    __syncthreads();

    // ---- preload A fragments (16 rows, full k=64) ----
    uint32_t A[8][4];
    #pragma unroll
    for (int ks = 0; ks < 8; ks++) {
        const float* qr = Qs + (m0 + gid) * QSTR + ks * 8 + tig;
        A[ks][0] = __float_as_uint(qr[0]);
        A[ks][1] = __float_as_uint(qr[8 * QSTR]);
        A[ks][2] = __float_as_uint(qr[4]);
        A[ks][3] = __float_as_uint(qr[8 * QSTR + 4]);
    }

    // ---- QK^T over 8 chunks of 64 key rows (double buffered) ----
    for (int kc = 0; kc < 8; kc++) {
        float* cur = KV + (kc & 1) * KVBUF;
        if (kc < 7) {
            load_chunk(KV + ((kc + 1) & 1) * KVBUF, kb, (kc + 1) * 64, KSTR, tid);
            CP_COMMIT;
        } else {
            // prefetch V chunk 0 into buf0 (free since kc=6), hides under softmax
            load_chunk(KV, vb, 0, VSTR, tid);
            CP_COMMIT;
        }
        CP_WAIT1;
        __syncthreads();

        float C[2][4];
        #pragma unroll
        for (int nt = 0; nt < 2; nt++)
            #pragma unroll
            for (int i = 0; i < 4; i++) C[nt][i] = 0.f;

        #pragma unroll
        for (int nt = 0; nt < 2; nt++) {
            const float* kr = cur + (cg * 16 + nt * 8 + gid) * KSTR + tig;
            #pragma unroll
            for (int ks = 0; ks < 8; ks++) {
                uint32_t b0 = f2tf32(kr[ks * 8]);
                uint32_t b1 = f2tf32(kr[ks * 8 + 4]);
                mma8(C[nt], A[ks][0], A[ks][1], A[ks][2], A[ks][3], b0, b1);
            }
        }
        #pragma unroll
        for (int nt = 0; nt < 2; nt++) {
            int col = kc * 64 + cg * 16 + nt * 8 + tig * 2;
            float* s0 = Sc + (m0 + gid) * SSTR + col;
            s0[0] = C[nt][0];
            s0[1] = C[nt][1];
            s0[8 * SSTR]     = C[nt][2];
            s0[8 * SSTR + 1] = C[nt][3];
        }
        __syncthreads();
    }

    // ---- masked softmax + head_mask; write attn; store P (tf32) ----
    for (int rr = 0; rr < 4; rr++) {
        int r    = w * 4 + rr;
        int qrow = q0 + r;
        float*     srow = Sc + r * SSTR;
        const int* mrow = amask + (long)qrow * 512;

        float sv[16];
        float mx = -INFINITY;
        #pragma unroll
        for (int j = 0; j < 16; j++) {
            int col = lane + j * 32;
            float s = srow[col];
            s = (mrow[col] != 0) ? s : -INFINITY;
            sv[j] = s;
            mx = fmaxf(mx, s);
        }
        #pragma unroll
        for (int o = 16; o; o >>= 1) mx = fmaxf(mx, __shfl_xor_sync(0xFFFFFFFFu, mx, o));

        float sum = 0.f;
        #pragma unroll
        for (int j = 0; j < 16; j++) {
            float e = __expf(sv[j] - mx);
            sv[j] = e;
            sum += e;
        }
        #pragma unroll
        for (int o = 16; o; o >>= 1) sum += __shfl_xor_sync(0xFFFFFFFFu, sum, o);
        float inv = 1.0f / sum;

        const float* hrow = hmask + (long)qrow * 512;
        float*       arow = ab + (long)qrow * 512;
        #pragma unroll
        for (int j = 0; j < 16; j++) {
            int col = lane + j * 32;
            float a = sv[j] * inv * hrow[col];
            arow[col] = a;
            srow[col] = __uint_as_float(f2tf32(a));
        }
    }
    __syncthreads();

    // ---- O = P @ V over 8 chunks (double buffered; chunk 0 already in flight) ----
    float O[2][4];
    #pragma unroll
    for (int nt = 0; nt < 2; nt++)
        #pragma unroll
        for (int i = 0; i < 4; i++) O[nt][i] = 0.f;

    for (int vc = 0; vc < 8; vc++) {
        float* cur = KV + (vc & 1) * KVBUF;
        if (vc < 7) {
            load_chunk(KV + ((vc + 1) & 1) * KVBUF, vb, (vc + 1) * 64, VSTR, tid);
            CP_COMMIT;
            CP_WAIT1;
        } else {
            CP_WAIT0;
        }
        __syncthreads();

        #pragma unroll
        for (int ks = 0; ks < 8; ks++) {
            const float* pr = Sc + (m0 + gid) * SSTR + vc * 64 + ks * 8 + tig;
            uint32_t a0 = __float_as_uint(pr[0]);
            uint32_t a1 = __float_as_uint(pr[8 * SSTR]);
            uint32_t a2 = __float_as_uint(pr[4]);
            uint32_t a3 = __float_as_uint(pr[8 * SSTR + 4]);
            const float* vr = cur + (ks * 8 + tig) * VSTR + cg * 16 + gid;
            #pragma unroll
            for (int nt = 0; nt < 2; nt++) {
                uint32_t b0 = f2tf32(vr[nt * 8]);
                uint32_t b1 = f2tf32(vr[4 * VSTR + nt * 8]);
                mma8(O[nt], a0, a1, a2, a3, b0, b1);
            }
        }
        __syncthreads();
    }

    // ---- write out tile ----
    #pragma unroll
    for (int nt = 0; nt < 2; nt++) {
        int col = cg * 16 + nt * 8 + tig * 2;
        float* o0 = ob + (long)(q0 + m0 + gid) * 512 + col;
        o0[0] = O[nt][0];
        o0[1] = O[nt][1];
        float* o1 = ob + (long)(q0 + m0 + gid + 8) * 512 + col;
        o1[0] = O[nt][2];
        o1[1] = O[nt][3];
    }
}

extern "C" void kernel_launch(void* const* d_in, const int* in_sizes, int n_in,
                              void* d_out, int out_size) {
    const float* q  = (const float*)d_in[0];
    const float* k  = (const float*)d_in[1];
    const float* v  = (const float*)d_in[2];
    const int*   am = (const int*)d_in[3];
    const float* hm = (const float*)d_in[4];

    float* out  = (float*)d_out;
    float* attn = out + (long)in_sizes[0];

    size_t smem = (size_t)SMEM_FLOATS * sizeof(float);
    cudaFuncSetAttribute(axial_attn_kernel,
                         cudaFuncAttributeMaxDynamicSharedMemorySize, (int)smem);

    dim3 grid(16, 512);   // x: 32-row query tiles, y: flattened batch B'
    axial_attn_kernel<<<grid, 256, smem>>>(q, k, v, am, hm, out, attn);
}

// round 3
// speedup vs baseline: 1.3733x; 1.1256x over previous
#include <cuda_runtime.h>
#include <cuda_fp16.h>
#include <cstdint>

// AxialAttention: 512 independent attention problems of [S=512, c=64].
// B' = outer*8 + W; q/k/v/out element (B', s, c) at outer*262144 + s*512 + W*64 + c.
// attn output [B',512,512] contiguous, placed after `out` in d_out.
// fp16 m16n8k16 MMA path (same 10-bit mantissa as tf32), 32 query rows/CTA,
// 256 threads, double-buffered cp.async K/V chunks (64 rows).

#define QSTRH 72          // Q smem row stride (halves)
#define KSTR 72           // K smem row stride (floats)
#define VSTR 76           // V smem row stride (floats)
#define SSTR 516          // scores smem row stride (floats)
#define QROWS 32
#define KVBUF (64*VSTR)   // floats per K/V buffer
#define SMEM_FLOATS (QROWS*QSTRH/2 + 2*KVBUF + QROWS*SSTR)

__device__ __forceinline__ uint32_t packh2(float a, float b) {
    __half2 h = __floats2half2_rn(a, b);
    return *reinterpret_cast<uint32_t*>(&h);
}

__device__ __forceinline__ void mma16(float* c,
        uint32_t a0, uint32_t a1, uint32_t a2, uint32_t a3,
        uint32_t b0, uint32_t b1) {
    asm volatile(
        "mma.sync.aligned.m16n8k16.row.col.f32.f16.f16.f32 "
        "{%0,%1,%2,%3},{%4,%5,%6,%7},{%8,%9},{%0,%1,%2,%3};\n"
        : "+f"(c[0]), "+f"(c[1]), "+f"(c[2]), "+f"(c[3])
        : "r"(a0), "r"(a1), "r"(a2), "r"(a3), "r"(b0), "r"(b1));
}

__device__ __forceinline__ void cp16(float* s, const float* g) {
    uint32_t sa = (uint32_t)__cvta_generic_to_shared(s);
    asm volatile("cp.async.cg.shared.global [%0], [%1], 16;\n" :: "r"(sa), "l"(g));
}
#define CP_COMMIT asm volatile("cp.async.commit_group;\n" ::: "memory")
#define CP_WAIT1  asm volatile("cp.async.wait_group 1;\n" ::: "memory")
#define CP_WAIT0  asm volatile("cp.async.wait_group 0;\n" ::: "memory")

// load a 64-row x 64-col fp32 chunk into smem (raw bits)
__device__ __forceinline__ void load_chunk(float* dst, const float* gb,
                                           int row0, int str, int tid) {
    #pragma unroll
    for (int i = 0; i < 4; i++) {
        int idx = tid + 256 * i;        // 1024 float4 total
        int r   = idx >> 4;
        int c4  = (idx & 15) << 2;
        cp16(dst + r * str + c4, gb + (long)(row0 + r) * 512 + c4);
    }
}

__global__ __launch_bounds__(256, 2)
void axial_attn_kernel(const float* __restrict__ q,
                       const float* __restrict__ k,
                       const float* __restrict__ v,
                       const int*   __restrict__ amask,
                       const float* __restrict__ hmask,
                       float* __restrict__ outp,
                       float* __restrict__ attnp)
{
    extern __shared__ float sm[];
    __half* Qs = (__half*)sm;                       // QROWS x QSTRH halves (pre-scaled)
    float*  KV = sm + QROWS * QSTRH / 2;            // 2 x KVBUF fp32 (cp.async)
    float*  Sc = KV + 2 * KVBUF;                    // QROWS x SSTR fp32 scores / half P overlay

    const int tid  = threadIdx.x;
    const int w    = tid >> 5;
    const int lane = tid & 31;
    const int gid  = lane >> 2;
    const int tig  = lane & 3;
    const int rg   = w >> 2;       // row group (0/1) -> 16 rows
    const int cg   = w & 3;        // col group (0..3) -> 16 cols within chunk
    const int m0   = rg * 16;

    const int Bp    = blockIdx.y;
    const int q0    = blockIdx.x * QROWS;
    const int outer = Bp >> 3;
    const int Wd    = Bp & 7;
    const long base = (long)outer * 262144 + (long)Wd * 64;

    const float* qb = q + base;
    const float* kb = k + base;
    const float* vb = v + base;
    float* ob = outp + base;
    float* ab = attnp + (long)Bp * 262144;

    // kick off K chunk 0 fetch immediately
    load_chunk(KV, kb, 0, KSTR, tid);
    CP_COMMIT;

    // ---- load Q tile (scale by 0.125, convert to half) ----
    #pragma unroll
    for (int i = 0; i < 2; i++) {
        int idx = tid + 256 * i;            // 512 float4
        int r   = idx >> 4;
        int c4  = (idx & 15) << 2;
        float4 t = *(const float4*)(qb + (long)(q0 + r) * 512 + c4);
        uint32_t h0 = packh2(t.x * 0.125f, t.y * 0.125f);
        uint32_t h1 = packh2(t.z * 0.125f, t.w * 0.125f);
        *(uint2*)(Qs + r * QSTRH + c4) = make_uint2(h0, h1);
    }
    __syncthreads();

    // ---- preload A fragments (16 rows, full k=64, 4 ksteps of 16) ----
    uint32_t A[4][4];
    #pragma unroll
    for (int ks = 0; ks < 4; ks++) {
        const __half* qr = Qs + (m0 + gid) * QSTRH + ks * 16 + 2 * tig;
        A[ks][0] = *(const uint32_t*)(qr);
        A[ks][1] = *(const uint32_t*)(qr + 8 * QSTRH);
        A[ks][2] = *(const uint32_t*)(qr + 8);
        A[ks][3] = *(const uint32_t*)(qr + 8 * QSTRH + 8);
    }

    // ---- QK^T over 8 chunks of 64 key rows (double buffered) ----
    for (int kc = 0; kc < 8; kc++) {
        float* cur = KV + (kc & 1) * KVBUF;
        if (kc < 7) {
            load_chunk(KV + ((kc + 1) & 1) * KVBUF, kb, (kc + 1) * 64, KSTR, tid);
            CP_COMMIT;
        } else {
            // prefetch V chunk 0 into buf0, hides under softmax
            load_chunk(KV, vb, 0, VSTR, tid);
            CP_COMMIT;
        }
        CP_WAIT1;
        __syncthreads();

        float C[2][4];
        #pragma unroll
        for (int nt = 0; nt < 2; nt++)
            #pragma unroll
            for (int i = 0; i < 4; i++) C[nt][i] = 0.f;

        #pragma unroll
        for (int nt = 0; nt < 2; nt++) {
            const float* kr = cur + (cg * 16 + nt * 8 + gid) * KSTR + 2 * tig;
            #pragma unroll
            for (int ks = 0; ks < 4; ks++) {
                float2 f0 = *(const float2*)(kr + ks * 16);
                float2 f1 = *(const float2*)(kr + ks * 16 + 8);
                uint32_t b0 = packh2(f0.x, f0.y);
                uint32_t b1 = packh2(f1.x, f1.y);
                mma16(C[nt], A[ks][0], A[ks][1], A[ks][2], A[ks][3], b0, b1);
            }
        }
        #pragma unroll
        for (int nt = 0; nt < 2; nt++) {
            int col = kc * 64 + cg * 16 + nt * 8 + tig * 2;
            float* s0 = Sc + (m0 + gid) * SSTR + col;
            s0[0] = C[nt][0];
            s0[1] = C[nt][1];
            s0[8 * SSTR]     = C[nt][2];
            s0[8 * SSTR + 1] = C[nt][3];
        }
        __syncthreads();
    }

    // ---- masked softmax + head_mask; write attn; store P as half2 overlay ----
    for (int rr = 0; rr < 4; rr++) {
        int r    = w * 4 + rr;
        int qrow = q0 + r;
        float*     srow = Sc + r * SSTR;
        const int* mrow = amask + (long)qrow * 512;

        float sv[16];
        float mx = -INFINITY;
        #pragma unroll
        for (int j = 0; j < 8; j++) {
            int col = 2 * lane + 64 * j;
            float2 s2 = *(const float2*)(srow + col);
            int2   m2 = *(const int2*)(mrow + col);
            float s0 = (m2.x != 0) ? s2.x : -INFINITY;
            float s1 = (m2.y != 0) ? s2.y : -INFINITY;
            sv[2*j]   = s0;
            sv[2*j+1] = s1;
            mx = fmaxf(mx, fmaxf(s0, s1));
        }
        #pragma unroll
        for (int o = 16; o; o >>= 1) mx = fmaxf(mx, __shfl_xor_sync(0xFFFFFFFFu, mx, o));

        float sum = 0.f;
        #pragma unroll
        for (int j = 0; j < 16; j++) {
            float e = __expf(sv[j] - mx);
            sv[j] = e;
            sum += e;
        }
        #pragma unroll
        for (int o = 16; o; o >>= 1) sum += __shfl_xor_sync(0xFFFFFFFFu, sum, o);
        float inv = 1.0f / sum;

        const float* hrow = hmask + (long)qrow * 512;
        float*       arow = ab + (long)qrow * 512;
        __syncwarp();   // all reads of srow done before half overlay writes
        #pragma unroll
        for (int j = 0; j < 8; j++) {
            int col = 2 * lane + 64 * j;
            float2 h2 = *(const float2*)(hrow + col);
            float a0 = sv[2*j]   * inv * h2.x;
            float a1 = sv[2*j+1] * inv * h2.y;
            *(float2*)(arow + col) = make_float2(a0, a1);
            ((uint32_t*)srow)[lane + 32 * j] = packh2(a0, a1);  // P overlay (half2)
        }
    }
    __syncthreads();

    // ---- O = P @ V over 8 chunks (double buffered; chunk 0 already in flight) ----
    float O[2][4];
    #pragma unroll
    for (int nt = 0; nt < 2; nt++)
        #pragma unroll
        for (int i = 0; i < 4; i++) O[nt][i] = 0.f;

    const uint32_t* Pr0 = (const uint32_t*)(Sc + (m0 + gid) * SSTR);
    const uint32_t* Pr1 = (const uint32_t*)(Sc + (m0 + gid + 8) * SSTR);

    for (int vc = 0; vc < 8; vc++) {
        float* cur = KV + (vc & 1) * KVBUF;
        if (vc < 7) {
            load_chunk(KV + ((vc + 1) & 1) * KVBUF, vb, (vc + 1) * 64, VSTR, tid);
            CP_COMMIT;
            CP_WAIT1;
        } else {
            CP_WAIT0;
        }
        __syncthreads();

        #pragma unroll
        for (int ks = 0; ks < 4; ks++) {
            int hidx = vc * 32 + ks * 8 + tig;     // half2 index within P row
            uint32_t a0 = Pr0[hidx];
            uint32_t a1 = Pr1[hidx];
            uint32_t a2 = Pr0[hidx + 4];
            uint32_t a3 = Pr1[hidx + 4];
            const float* vr = cur + (ks * 16 + 2 * tig) * VSTR + cg * 16 + gid;
            #pragma unroll
            for (int nt = 0; nt < 2; nt++) {
                uint32_t b0 = packh2(vr[nt * 8],            vr[VSTR + nt * 8]);
                uint32_t b1 = packh2(vr[8 * VSTR + nt * 8], vr[9 * VSTR + nt * 8]);
                mma16(O[nt], a0, a1, a2, a3, b0, b1);
            }
        }
        __syncthreads();
    }

    // ---- write out tile ----
    #pragma unroll
    for (int nt = 0; nt < 2; nt++) {
        int col = cg * 16 + nt * 8 + tig * 2;
        float* o0 = ob + (long)(q0 + m0 + gid) * 512 + col;
        o0[0] = O[nt][0];
        o0[1] = O[nt][1];
        float* o1 = ob + (long)(q0 + m0 + gid + 8) * 512 + col;
        o1[0] = O[nt][2];
        o1[1] = O[nt][3];
    }
}

extern "C" void kernel_launch(void* const* d_in, const int* in_sizes, int n_in,
                              void* d_out, int out_size) {
    const float* q  = (const float*)d_in[0];
    const float* k  = (const float*)d_in[1];
    const float* v  = (const float*)d_in[2];
    const int*   am = (const int*)d_in[3];
    const float* hm = (const float*)d_in[4];

    float* out  = (float*)d_out;
    float* attn = out + (long)in_sizes[0];

    size_t smem = (size_t)SMEM_FLOATS * sizeof(float);
    cudaFuncSetAttribute(axial_attn_kernel,
                         cudaFuncAttributeMaxDynamicSharedMemorySize, (int)smem);

    dim3 grid(16, 512);   // x: 32-row query tiles, y: flattened batch B'
    axial_attn_kernel<<<grid, 256, smem>>>(q, k, v, am, hm, out, attn);
}